// round 8
// baseline (speedup 1.0000x reference)
#include <cuda_runtime.h>
#include <cuda_fp16.h>
#include <cstdint>

#define D_VOCAB 262
#define D_EMB   128
#define NTAP    5
#define CW      16
#define NSEQ    32768
#define NCHUNK  74
#define THREADS 512
// main smem: [NTAP*D_VOCAB] rows of 64 channels (8 x uint4) = 167,680 bytes
#define SMEM_BYTES (NTAP * D_VOCAB * 32 * 4)
// uint4-unit stride of one tap plane: 262 rows * 8 uint4
#define TAPSTRIDE16 (D_VOCAB * 8)

// precompute smem: ws[i][k*64+eh], padded row stride 324 floats
#define WROW 324
#define PRE_SMEM (D_EMB * WROW * 4)   // 165,888 B
#define PRE_THREADS 320

// fp16 contrib table: [tap][vocab][emb]
__device__ __align__(16) __half g_tab[NTAP * D_VOCAB * D_EMB];

// ---------------------------------------------------------------------------
// Fused transpose+precompute:
//   contrib[k][v][e] = sum_i conv_w[e,i,k] * emb[v,i]  (fp32 -> fp16)
// Grid (17, 2): x = 16-vocab group, y = 64-e half. 320 threads = (k, eh).
// Phase 1: stage conv_w rows e0..e0+63 (160 KB) coalesced, transposed into
//          smem ws[i][k*64+eh]. Phase 2: thread (k,eh) FMAs over i against
//          broadcast emb float4 reads for 16 vocab rows.
// ---------------------------------------------------------------------------
__global__ void __launch_bounds__(PRE_THREADS, 1)
precompute_fused(const float* __restrict__ conv_w,
                 const float* __restrict__ emb) {
    extern __shared__ float ws[];
    const int tid = threadIdx.x;
    const int v0 = blockIdx.x * 16;
    const int e0 = blockIdx.y * 64;

    // Stage: 64 e-rows x 640 floats = 10240 float4, coalesced.
    const float4* __restrict__ cw4 = (const float4*)conv_w;
    for (int idx = tid; idx < 64 * 160; idx += PRE_THREADS) {
        const int r = idx / 160;       // e-row within half
        const int c = idx % 160;       // float4 within row
        float4 w = __ldg(&cw4[(size_t)(e0 + r) * 160 + c]);
        const int j = 4 * c;           // flat (i*5+k) index
        ws[((j + 0) / 5) * WROW + ((j + 0) % 5) * 64 + r] = w.x;
        ws[((j + 1) / 5) * WROW + ((j + 1) % 5) * 64 + r] = w.y;
        ws[((j + 2) / 5) * WROW + ((j + 2) % 5) * 64 + r] = w.z;
        ws[((j + 3) / 5) * WROW + ((j + 3) % 5) * 64 + r] = w.w;
    }
    __syncthreads();

    const int k = tid / 64;            // 0..4
    const int eh = tid % 64;
    const float* __restrict__ wcol = ws + k * 64 + eh;
    const float4* __restrict__ emb4 = (const float4*)emb;

    float acc[16];
    #pragma unroll
    for (int v = 0; v < 16; ++v) acc[v] = 0.f;

    for (int i4 = 0; i4 < 32; ++i4) {
        const float w0 = wcol[(i4 * 4 + 0) * WROW];
        const float w1 = wcol[(i4 * 4 + 1) * WROW];
        const float w2 = wcol[(i4 * 4 + 2) * WROW];
        const float w3 = wcol[(i4 * 4 + 3) * WROW];
        #pragma unroll
        for (int v = 0; v < 16; ++v) {
            const int vv = v0 + v;
            if (vv < D_VOCAB) {
                float4 em = __ldg(&emb4[vv * 32 + i4]);
                acc[v] = fmaf(em.x, w0, acc[v]);
                acc[v] = fmaf(em.y, w1, acc[v]);
                acc[v] = fmaf(em.z, w2, acc[v]);
                acc[v] = fmaf(em.w, w3, acc[v]);
            }
        }
    }

    #pragma unroll
    for (int v = 0; v < 16; ++v) {
        const int vv = v0 + v;
        if (vv < D_VOCAB)
            g_tab[(k * D_VOCAB + vv) * D_EMB + e0 + eh] = __float2half(acc[v]);
    }
}

// ---------------------------------------------------------------------------
// half2 x4 helpers on uint4-packed fp16
// ---------------------------------------------------------------------------
__device__ __forceinline__ uint4 h2add4(uint4 a, uint4 b) {
    uint4 r;
    *(__half2*)&r.x = __hadd2(*(const __half2*)&a.x, *(const __half2*)&b.x);
    *(__half2*)&r.y = __hadd2(*(const __half2*)&a.y, *(const __half2*)&b.y);
    *(__half2*)&r.z = __hadd2(*(const __half2*)&a.z, *(const __half2*)&b.z);
    *(__half2*)&r.w = __hadd2(*(const __half2*)&a.w, *(const __half2*)&b.w);
    return r;
}
__device__ __forceinline__ uint4 h2max4(uint4 a, uint4 b) {
    uint4 r;
    *(__half2*)&r.x = __hmax2(*(const __half2*)&a.x, *(const __half2*)&b.x);
    *(__half2*)&r.y = __hmax2(*(const __half2*)&a.y, *(const __half2*)&b.y);
    *(__half2*)&r.z = __hmax2(*(const __half2*)&a.z, *(const __half2*)&b.z);
    *(__half2*)&r.w = __hmax2(*(const __half2*)&a.w, *(const __half2*)&b.w);
    return r;
}

// ---------------------------------------------------------------------------
// Main kernel — R5 configuration (measured 27.3 us).
// Grid (74, 2): x = sequence chunk (443 seqs), y = 64-ch group.
// CTA stages its 5x262x64 fp16 table slice (164 KB smem), 1 CTA/SM, 1 wave.
// 512 threads = 16 warps/SM, regs unconstrained (~114) funding LDS ILP.
// Quarter-warp split: 4 seqs per warp-iter; lane owns 8 channels (16 B) ->
// LDS.128 gathers, conflict-free, 4 chains. Id loads software-pipelined.
// ---------------------------------------------------------------------------
__global__ void __launch_bounds__(THREADS, 1)
conv_char_kernel(const int* __restrict__ ids_raw,
                 const float* __restrict__ conv_b,
                 float* __restrict__ out) {
    extern __shared__ uint4 s_tab16[];
    const int g = blockIdx.y;
    const int lane = threadIdx.x & 31;
    const int warp = threadIdx.x >> 5;
    const int l7 = lane & 7;
    const int q = lane >> 3;             // 0..3: which sequence of the group

    // Per-warp int64-vs-int32 detection (no shared, no sync needed).
    int s2;
    {
        int v = ids_raw[2 * lane + 1] | ids_raw[64 + 2 * lane + 1];
        s2 = (__ballot_sync(0xffffffffu, v != 0) == 0u) ? 1 : 0;
    }

    const int chunk = (NSEQ + NCHUNK - 1) / NCHUNK;  // 443
    const int base = blockIdx.x * chunk;
    const int end = min(base + chunk, NSEQ);
    const int step = 4 * (THREADS / 32);             // 64

    // Prefetch first iteration's raw id words BEFORE staging (overlaps).
    uint4 raw[8];
    {
        const int nc = min(base + 4 * warp + q, end - 1);
        if (s2) {
            const uint4* p = (const uint4*)(ids_raw + (size_t)nc * 32);
            #pragma unroll
            for (int j = 0; j < 8; ++j) raw[j] = __ldg(&p[j]);
        } else {
            const uint4* p = (const uint4*)(ids_raw + (size_t)nc * 16);
            #pragma unroll
            for (int j = 0; j < 4; ++j) raw[j] = __ldg(&p[j]);
        }
    }

    // Stage table slice: coalesced uint4 copies (10480 x 16 B).
    {
        const char* gb = (const char*)g_tab;
        for (int idx = threadIdx.x; idx < NTAP * D_VOCAB * 8; idx += THREADS) {
            int r = idx >> 3, c = idx & 7;
            s_tab16[idx] = *(const uint4*)(gb + (size_t)r * 256 + g * 128 + c * 16);
        }
    }
    __syncthreads();

    for (int n0 = base + 4 * warp; n0 < end; n0 += step) {
        const int nsel = n0 + q;

        // Convert raw -> gather indices a[c] = id*8 + l7.
        int a[CW];
        if (s2) {
            #pragma unroll
            for (int j = 0; j < 8; ++j) {
                a[2 * j]     = (int)raw[j].x * 8 + l7;
                a[2 * j + 1] = (int)raw[j].z * 8 + l7;
            }
        } else {
            #pragma unroll
            for (int j = 0; j < 4; ++j) {
                a[4 * j]     = (int)raw[j].x * 8 + l7;
                a[4 * j + 1] = (int)raw[j].y * 8 + l7;
                a[4 * j + 2] = (int)raw[j].z * 8 + l7;
                a[4 * j + 3] = (int)raw[j].w * 8 + l7;
            }
        }

        // Issue next iteration's id loads now; latency hides under t-loop.
        {
            const int nn = n0 + step + q;
            const int nc = min(nn < end ? nn : (end - 1), end - 1);
            if (s2) {
                const uint4* p = (const uint4*)(ids_raw + (size_t)nc * 32);
                #pragma unroll
                for (int j = 0; j < 8; ++j) raw[j] = __ldg(&p[j]);
            } else {
                const uint4* p = (const uint4*)(ids_raw + (size_t)nc * 16);
                #pragma unroll
                for (int j = 0; j < 4; ++j) raw[j] = __ldg(&p[j]);
            }
        }

        // Even/odd-t max chains on 8 channels (4 half2) per lane.
        uint4 me, mo;
        #pragma unroll
        for (int t = 0; t < CW; ++t) {
            const int klo = (t < 2) ? (2 - t) : 0;
            const int khi = (t > CW - 3) ? (CW + 1 - t) : NTAP - 1;  // inclusive

            uint4 s[NTAP];
            #pragma unroll
            for (int k = 0; k < NTAP; ++k) {
                if (k < klo || k > khi) continue;
                s[k] = s_tab16[k * TAPSTRIDE16 + a[t + k - 2]];
            }

            uint4 y;
            const int nv = khi - klo + 1;
            if (nv == 5) {
                y = h2add4(h2add4(h2add4(s[0], s[1]), h2add4(s[2], s[3])), s[4]);
            } else if (nv == 4) {
                y = h2add4(h2add4(s[klo], s[klo + 1]), h2add4(s[klo + 2], s[klo + 3]));
            } else {  // nv == 3
                y = h2add4(h2add4(s[klo], s[klo + 1]), s[klo + 2]);
            }

            if (t == 0)      me = y;
            else if (t == 1) mo = y;
            else if ((t & 1) == 0) me = h2max4(me, y);
            else                   mo = h2max4(mo, y);
        }
        const uint4 m = h2max4(me, mo);

        if (nsel < end) {
            // Bias loaded here (L1-resident), not held in registers.
            const float4 bias0 = __ldg((const float4*)(conv_b + g * 64 + l7 * 8));
            const float4 bias1 = __ldg((const float4*)(conv_b + g * 64 + l7 * 8 + 4));
            float2 c0 = __half22float2(*(const __half2*)&m.x);
            float2 c1 = __half22float2(*(const __half2*)&m.y);
            float2 c2 = __half22float2(*(const __half2*)&m.z);
            float2 c3 = __half22float2(*(const __half2*)&m.w);
            float4 o0, o1;
            o0.x = c0.x + bias0.x; o0.y = c0.y + bias0.y;
            o0.z = c1.x + bias0.z; o0.w = c1.y + bias0.w;
            o1.x = c2.x + bias1.x; o1.y = c2.y + bias1.y;
            o1.z = c3.x + bias1.z; o1.w = c3.y + bias1.w;
            float* op = out + (size_t)nsel * D_EMB + g * 64 + l7 * 8;
            *(float4*)op = o0;
            *(float4*)(op + 4) = o1;
        }
    }
}

// ---------------------------------------------------------------------------
extern "C" void kernel_launch(void* const* d_in, const int* in_sizes, int n_in,
                              void* d_out, int out_size) {
    const int* input = nullptr;
    const float* emb = nullptr;
    const float* conv_w = nullptr;
    const float* conv_b = nullptr;
    for (int i = 0; i < n_in; ++i) {
        switch (in_sizes[i]) {
            case 524288: input  = (const int*)d_in[i];   break;  // ids [128,256,16]
            case 33536:  emb    = (const float*)d_in[i]; break;  // [262,128]
            case 81920:  conv_w = (const float*)d_in[i]; break;  // [128,128,5]
            case 128:    conv_b = (const float*)d_in[i]; break;  // [128]
            default: break;  // lengths (32768) unused
        }
    }

    cudaFuncSetAttribute(precompute_fused,
                         cudaFuncAttributeMaxDynamicSharedMemorySize, PRE_SMEM);
    precompute_fused<<<dim3(17, 2), PRE_THREADS, PRE_SMEM>>>(conv_w, emb);

    cudaFuncSetAttribute(conv_char_kernel,
                         cudaFuncAttributeMaxDynamicSharedMemorySize, SMEM_BYTES);
    conv_char_kernel<<<dim3(NCHUNK, 2), THREADS, SMEM_BYTES>>>(
        input, conv_b, (float*)d_out);
}

// round 9
// speedup vs baseline: 1.2145x; 1.2145x over previous
#include <cuda_runtime.h>
#include <cuda_fp16.h>
#include <cstdint>

#define D_VOCAB 262
#define D_EMB   128
#define NTAP    5
#define CW      16
#define NSEQ    32768
#define NCHUNK  74
#define THREADS 576
// main smem: [NTAP*D_VOCAB] rows of 64 channels (8 x uint4) = 167,680 bytes
#define SMEM_BYTES (NTAP * D_VOCAB * 32 * 4)
// uint4-unit stride of one tap plane: 262 rows * 8 uint4
#define TAPSTRIDE16 (D_VOCAB * 8)

// precompute smem: ws[i][k*32+eL] padded row stride 164 floats
#define WROW 164
#define PRE_SMEM (D_EMB * WROW * 4)   // 83,968 B
#define PRE_THREADS 160

// fp16 contrib table: [tap][vocab][emb]
__device__ __align__(16) __half g_tab[NTAP * D_VOCAB * D_EMB];

// ---------------------------------------------------------------------------
// Fused transpose+precompute (R5 configuration — measured 8.0 us overhead):
//   contrib[k][v][e] = sum_i conv_w[e,i,k] * emb[v,i]  (fp32 -> fp16)
// Grid (33, 4): x = 8-vocab group, y = 32-e group. 160 threads.
// ---------------------------------------------------------------------------
__global__ void __launch_bounds__(PRE_THREADS, 1)
precompute_fused(const float* __restrict__ conv_w,
                 const float* __restrict__ emb) {
    extern __shared__ float ws[];
    const int tid = threadIdx.x;
    const int v0 = blockIdx.x * 8;
    const int e0 = blockIdx.y * 32;

    // Stage: 32 e-rows x 640 floats. Per r: 160 threads x float4 = whole row.
    const float4* __restrict__ cw4 = (const float4*)conv_w;
    #pragma unroll 4
    for (int r = 0; r < 32; ++r) {
        float4 w = __ldg(&cw4[(size_t)(e0 + r) * 160 + tid]);
        const int j = 4 * tid;
        ws[((j + 0) / 5) * WROW + ((j + 0) % 5) * 32 + r] = w.x;
        ws[((j + 1) / 5) * WROW + ((j + 1) % 5) * 32 + r] = w.y;
        ws[((j + 2) / 5) * WROW + ((j + 2) % 5) * 32 + r] = w.z;
        ws[((j + 3) / 5) * WROW + ((j + 3) % 5) * 32 + r] = w.w;
    }
    __syncthreads();

    const int k = tid >> 5;          // 0..4
    const int eL = tid & 31;
    const float* __restrict__ wcol = ws + k * 32 + eL;
    const float4* __restrict__ emb4 = (const float4*)emb;

    float acc[8];
    #pragma unroll
    for (int v = 0; v < 8; ++v) acc[v] = 0.f;

    #pragma unroll 4
    for (int i4 = 0; i4 < 32; ++i4) {
        const float w0 = wcol[(i4 * 4 + 0) * WROW];
        const float w1 = wcol[(i4 * 4 + 1) * WROW];
        const float w2 = wcol[(i4 * 4 + 2) * WROW];
        const float w3 = wcol[(i4 * 4 + 3) * WROW];
        #pragma unroll
        for (int v = 0; v < 8; ++v) {
            const int vv = v0 + v;
            if (vv < D_VOCAB) {
                float4 em = __ldg(&emb4[vv * 32 + i4]);
                acc[v] = fmaf(em.x, w0, acc[v]);
                acc[v] = fmaf(em.y, w1, acc[v]);
                acc[v] = fmaf(em.z, w2, acc[v]);
                acc[v] = fmaf(em.w, w3, acc[v]);
            }
        }
    }

    #pragma unroll
    for (int v = 0; v < 8; ++v) {
        const int vv = v0 + v;
        if (vv < D_VOCAB)
            g_tab[(k * D_VOCAB + vv) * D_EMB + e0 + eL] = __float2half(acc[v]);
    }
}

// ---------------------------------------------------------------------------
// half2 x4 helpers on uint4-packed fp16
// ---------------------------------------------------------------------------
__device__ __forceinline__ uint4 h2add4(uint4 a, uint4 b) {
    uint4 r;
    *(__half2*)&r.x = __hadd2(*(const __half2*)&a.x, *(const __half2*)&b.x);
    *(__half2*)&r.y = __hadd2(*(const __half2*)&a.y, *(const __half2*)&b.y);
    *(__half2*)&r.z = __hadd2(*(const __half2*)&a.z, *(const __half2*)&b.z);
    *(__half2*)&r.w = __hadd2(*(const __half2*)&a.w, *(const __half2*)&b.w);
    return r;
}
__device__ __forceinline__ uint4 h2max4(uint4 a, uint4 b) {
    uint4 r;
    *(__half2*)&r.x = __hmax2(*(const __half2*)&a.x, *(const __half2*)&b.x);
    *(__half2*)&r.y = __hmax2(*(const __half2*)&a.y, *(const __half2*)&b.y);
    *(__half2*)&r.z = __hmax2(*(const __half2*)&a.z, *(const __half2*)&b.z);
    *(__half2*)&r.w = __hmax2(*(const __half2*)&a.w, *(const __half2*)&b.w);
    return r;
}

// ---------------------------------------------------------------------------
// Main kernel — R5 recipe at 576 threads (18 warps/SM, reg cap 112 >= 109).
// Grid (74, 2): x = sequence chunk (443 seqs), y = 64-ch group.
// CTA stages its 5x262x64 fp16 table slice (164 KB smem), 1 CTA/SM, 1 wave.
// Quarter-warp split: 4 seqs per warp-iter; lane owns 8 channels (16 B) ->
// LDS.128 gathers, conflict-free, 4 chains. Id loads software-pipelined.
// ---------------------------------------------------------------------------
__global__ void __launch_bounds__(THREADS, 1)
conv_char_kernel(const int* __restrict__ ids_raw,
                 const float* __restrict__ conv_b,
                 float* __restrict__ out) {
    extern __shared__ uint4 s_tab16[];
    const int g = blockIdx.y;
    const int lane = threadIdx.x & 31;
    const int warp = threadIdx.x >> 5;
    const int l7 = lane & 7;
    const int q = lane >> 3;             // 0..3: which sequence of the group

    // Per-warp int64-vs-int32 detection (no shared, no sync needed).
    int s2;
    {
        int v = ids_raw[2 * lane + 1] | ids_raw[64 + 2 * lane + 1];
        s2 = (__ballot_sync(0xffffffffu, v != 0) == 0u) ? 1 : 0;
    }

    const int chunk = (NSEQ + NCHUNK - 1) / NCHUNK;  // 443
    const int base = blockIdx.x * chunk;
    const int end = min(base + chunk, NSEQ);
    const int step = 4 * (THREADS / 32);             // 72

    // Prefetch first iteration's raw id words BEFORE staging (overlaps).
    uint4 raw[8];
    {
        const int nc = min(base + 4 * warp + q, end - 1);
        if (s2) {
            const uint4* p = (const uint4*)(ids_raw + (size_t)nc * 32);
            #pragma unroll
            for (int j = 0; j < 8; ++j) raw[j] = __ldg(&p[j]);
        } else {
            const uint4* p = (const uint4*)(ids_raw + (size_t)nc * 16);
            #pragma unroll
            for (int j = 0; j < 4; ++j) raw[j] = __ldg(&p[j]);
        }
    }

    // Stage table slice: coalesced uint4 copies (10480 x 16 B).
    {
        const char* gb = (const char*)g_tab;
        for (int idx = threadIdx.x; idx < NTAP * D_VOCAB * 8; idx += THREADS) {
            int r = idx >> 3, c = idx & 7;
            s_tab16[idx] = *(const uint4*)(gb + (size_t)r * 256 + g * 128 + c * 16);
        }
    }
    __syncthreads();

    for (int n0 = base + 4 * warp; n0 < end; n0 += step) {
        const int nsel = n0 + q;

        // Convert raw -> gather indices a[c] = id*8 + l7.
        int a[CW];
        if (s2) {
            #pragma unroll
            for (int j = 0; j < 8; ++j) {
                a[2 * j]     = (int)raw[j].x * 8 + l7;
                a[2 * j + 1] = (int)raw[j].z * 8 + l7;
            }
        } else {
            #pragma unroll
            for (int j = 0; j < 4; ++j) {
                a[4 * j]     = (int)raw[j].x * 8 + l7;
                a[4 * j + 1] = (int)raw[j].y * 8 + l7;
                a[4 * j + 2] = (int)raw[j].z * 8 + l7;
                a[4 * j + 3] = (int)raw[j].w * 8 + l7;
            }
        }

        // Issue next iteration's id loads now; latency hides under t-loop.
        {
            const int nn = n0 + step + q;
            const int nc = min(nn < end ? nn : (end - 1), end - 1);
            if (s2) {
                const uint4* p = (const uint4*)(ids_raw + (size_t)nc * 32);
                #pragma unroll
                for (int j = 0; j < 8; ++j) raw[j] = __ldg(&p[j]);
            } else {
                const uint4* p = (const uint4*)(ids_raw + (size_t)nc * 16);
                #pragma unroll
                for (int j = 0; j < 4; ++j) raw[j] = __ldg(&p[j]);
            }
        }

        // Even/odd-t max chains on 8 channels (4 half2) per lane.
        uint4 me, mo;
        #pragma unroll
        for (int t = 0; t < CW; ++t) {
            const int klo = (t < 2) ? (2 - t) : 0;
            const int khi = (t > CW - 3) ? (CW + 1 - t) : NTAP - 1;  // inclusive

            uint4 s[NTAP];
            #pragma unroll
            for (int k = 0; k < NTAP; ++k) {
                if (k < klo || k > khi) continue;
                s[k] = s_tab16[k * TAPSTRIDE16 + a[t + k - 2]];
            }

            uint4 y;
            const int nv = khi - klo + 1;
            if (nv == 5) {
                y = h2add4(h2add4(h2add4(s[0], s[1]), h2add4(s[2], s[3])), s[4]);
            } else if (nv == 4) {
                y = h2add4(h2add4(s[klo], s[klo + 1]), h2add4(s[klo + 2], s[klo + 3]));
            } else {  // nv == 3
                y = h2add4(h2add4(s[klo], s[klo + 1]), s[klo + 2]);
            }

            if (t == 0)      me = y;
            else if (t == 1) mo = y;
            else if ((t & 1) == 0) me = h2max4(me, y);
            else                   mo = h2max4(mo, y);
        }
        const uint4 m = h2max4(me, mo);

        if (nsel < end) {
            // Bias loaded here (L1-resident), not held in registers.
            const float4 bias0 = __ldg((const float4*)(conv_b + g * 64 + l7 * 8));
            const float4 bias1 = __ldg((const float4*)(conv_b + g * 64 + l7 * 8 + 4));
            float2 c0 = __half22float2(*(const __half2*)&m.x);
            float2 c1 = __half22float2(*(const __half2*)&m.y);
            float2 c2 = __half22float2(*(const __half2*)&m.z);
            float2 c3 = __half22float2(*(const __half2*)&m.w);
            float4 o0, o1;
            o0.x = c0.x + bias0.x; o0.y = c0.y + bias0.y;
            o0.z = c1.x + bias0.z; o0.w = c1.y + bias0.w;
            o1.x = c2.x + bias1.x; o1.y = c2.y + bias1.y;
            o1.z = c3.x + bias1.z; o1.w = c3.y + bias1.w;
            float* op = out + (size_t)nsel * D_EMB + g * 64 + l7 * 8;
            *(float4*)op = o0;
            *(float4*)(op + 4) = o1;
        }
    }
}

// ---------------------------------------------------------------------------
extern "C" void kernel_launch(void* const* d_in, const int* in_sizes, int n_in,
                              void* d_out, int out_size) {
    const int* input = nullptr;
    const float* emb = nullptr;
    const float* conv_w = nullptr;
    const float* conv_b = nullptr;
    for (int i = 0; i < n_in; ++i) {
        switch (in_sizes[i]) {
            case 524288: input  = (const int*)d_in[i];   break;  // ids [128,256,16]
            case 33536:  emb    = (const float*)d_in[i]; break;  // [262,128]
            case 81920:  conv_w = (const float*)d_in[i]; break;  // [128,128,5]
            case 128:    conv_b = (const float*)d_in[i]; break;  // [128]
            default: break;  // lengths (32768) unused
        }
    }

    cudaFuncSetAttribute(precompute_fused,
                         cudaFuncAttributeMaxDynamicSharedMemorySize, PRE_SMEM);
    precompute_fused<<<dim3(33, 4), PRE_THREADS, PRE_SMEM>>>(conv_w, emb);

    cudaFuncSetAttribute(conv_char_kernel,
                         cudaFuncAttributeMaxDynamicSharedMemorySize, SMEM_BYTES);
    conv_char_kernel<<<dim3(NCHUNK, 2), THREADS, SMEM_BYTES>>>(
        input, conv_b, (float*)d_out);
}

// round 10
// speedup vs baseline: 1.2734x; 1.0486x over previous
#include <cuda_runtime.h>
#include <cuda_fp16.h>
#include <cstdint>

#define D_VOCAB 262
#define D_EMB   128
#define NTAP    5
#define CW      16
#define NSEQ    32768
#define NCHUNK  74
#define THREADS 512
#define NCTAS   (NCHUNK * 2)            // 148
// smem: table region [NTAP*D_VOCAB] rows of 64 ch (8 x uint4) = 167,680 B
#define SMEM_BYTES (NTAP * D_VOCAB * 32 * 4)
// uint4-unit stride of one tap plane: 262 rows * 8 uint4
#define TAPSTRIDE16 (D_VOCAB * 8)
// phase-1 weight scratch: ws[i][k*32+eL], row stride 164 floats (83,968 B)
#define WROW 164

// fp16 contrib table: [tap][vocab][emb]
__device__ __align__(16) __half g_tab[NTAP * D_VOCAB * D_EMB];
// grid-wide ticket barrier (monotonic across graph replays; no reset needed)
__device__ unsigned g_bar;

// ---------------------------------------------------------------------------
// half2 x4 helpers on uint4-packed fp16
// ---------------------------------------------------------------------------
__device__ __forceinline__ uint4 h2add4(uint4 a, uint4 b) {
    uint4 r;
    *(__half2*)&r.x = __hadd2(*(const __half2*)&a.x, *(const __half2*)&b.x);
    *(__half2*)&r.y = __hadd2(*(const __half2*)&a.y, *(const __half2*)&b.y);
    *(__half2*)&r.z = __hadd2(*(const __half2*)&a.z, *(const __half2*)&b.z);
    *(__half2*)&r.w = __hadd2(*(const __half2*)&a.w, *(const __half2*)&b.w);
    return r;
}
__device__ __forceinline__ uint4 h2max4(uint4 a, uint4 b) {
    uint4 r;
    *(__half2*)&r.x = __hmax2(*(const __half2*)&a.x, *(const __half2*)&b.x);
    *(__half2*)&r.y = __hmax2(*(const __half2*)&a.y, *(const __half2*)&b.y);
    *(__half2*)&r.z = __hmax2(*(const __half2*)&a.z, *(const __half2*)&b.z);
    *(__half2*)&r.w = __hmax2(*(const __half2*)&a.w, *(const __half2*)&b.w);
    return r;
}

// ---------------------------------------------------------------------------
// Fused kernel. Grid (74, 2) = 148 CTAs, 164 KB smem -> 1 CTA/SM, all
// co-resident (GB300 has 152 SMs) -> device-wide ticket barrier is safe.
// Phase 1: CTAs jointly build g_tab[k][v][e] = sum_i conv_w[e,i,k]*emb[v,i].
//   CTA -> (eg = cta&3: 32-e group, vg = cta>>2: 8-v group; vg>=33 idle).
//   conv_w e-slice staged TRANSPOSED into smem (coalesced), then 320 threads
//   (vh,k,eL) each produce 4 vocab rows' worth of one (k,e) column.
// Barrier: monotonic ticket barrier (replay-safe under graph capture).
// Phase 2: R5 main loop (measured 27.3us) — table staged from hot L2.
// ---------------------------------------------------------------------------
__global__ void __launch_bounds__(THREADS, 1)
conv_char_fused(const int* __restrict__ ids_raw,
                const float* __restrict__ emb,
                const float* __restrict__ conv_w,
                const float* __restrict__ conv_b,
                float* __restrict__ out) {
    extern __shared__ uint4 s_tab16[];
    float* ws = (float*)s_tab16;                 // phase-1 alias (84 KB)
    const int g = blockIdx.y;
    const int lane = threadIdx.x & 31;
    const int warp = threadIdx.x >> 5;
    const int l7 = lane & 7;
    const int q = lane >> 3;

    // -- s2 detection + first id prefetch (overlaps phase 1) ---------------
    int s2;
    {
        int v = ids_raw[2 * lane + 1] | ids_raw[64 + 2 * lane + 1];
        s2 = (__ballot_sync(0xffffffffu, v != 0) == 0u) ? 1 : 0;
    }
    const int chunk = (NSEQ + NCHUNK - 1) / NCHUNK;  // 443
    const int base = blockIdx.x * chunk;
    const int end = min(base + chunk, NSEQ);
    const int step = 4 * (THREADS / 32);             // 64

    uint4 raw[8];
    {
        const int nc = min(base + 4 * warp + q, end - 1);
        if (s2) {
            const uint4* p = (const uint4*)(ids_raw + (size_t)nc * 32);
            #pragma unroll
            for (int j = 0; j < 8; ++j) raw[j] = __ldg(&p[j]);
        } else {
            const uint4* p = (const uint4*)(ids_raw + (size_t)nc * 16);
            #pragma unroll
            for (int j = 0; j < 4; ++j) raw[j] = __ldg(&p[j]);
        }
    }

    // ===== Phase 1: build this CTA's slice of g_tab =======================
    {
        const int cta = blockIdx.y * NCHUNK + blockIdx.x;   // 0..147
        const int eg = cta & 3;            // 32-e group
        const int vg = cta >> 2;           // 8-v group (>=33 -> idle)
        const int e0 = eg * 32;
        const int v0 = vg * 8;

        // Stage conv_w rows e0..e0+31 transposed: ws[i*WROW + k*32 + r].
        const float4* __restrict__ cw4 = (const float4*)conv_w;
        for (int idx = threadIdx.x; idx < 32 * 160; idx += THREADS) {
            const int r = idx / 160;
            const int c = idx % 160;
            float4 w = __ldg(&cw4[(size_t)(e0 + r) * 160 + c]);
            const int j = 4 * c;
            ws[((j + 0) / 5) * WROW + ((j + 0) % 5) * 32 + r] = w.x;
            ws[((j + 1) / 5) * WROW + ((j + 1) % 5) * 32 + r] = w.y;
            ws[((j + 2) / 5) * WROW + ((j + 2) % 5) * 32 + r] = w.z;
            ws[((j + 3) / 5) * WROW + ((j + 3) % 5) * 32 + r] = w.w;
        }
        __syncthreads();

        if (threadIdx.x < 320 && v0 < D_VOCAB) {
            const int vh = threadIdx.x / 160;          // 0..1
            const int k = (threadIdx.x % 160) >> 5;    // 0..4
            const int eL = threadIdx.x & 31;
            const float* __restrict__ wcol = ws + k * 32 + eL;
            const float4* __restrict__ emb4 = (const float4*)emb;
            const int vb = v0 + vh * 4;

            float acc[4];
            #pragma unroll
            for (int v = 0; v < 4; ++v) acc[v] = 0.f;

            #pragma unroll 4
            for (int i4 = 0; i4 < 32; ++i4) {
                const float w0 = wcol[(i4 * 4 + 0) * WROW];
                const float w1 = wcol[(i4 * 4 + 1) * WROW];
                const float w2 = wcol[(i4 * 4 + 2) * WROW];
                const float w3 = wcol[(i4 * 4 + 3) * WROW];
                #pragma unroll
                for (int v = 0; v < 4; ++v) {
                    const int vv = vb + v;
                    if (vv < D_VOCAB) {
                        float4 em = __ldg(&emb4[vv * 32 + i4]);
                        acc[v] = fmaf(em.x, w0, acc[v]);
                        acc[v] = fmaf(em.y, w1, acc[v]);
                        acc[v] = fmaf(em.z, w2, acc[v]);
                        acc[v] = fmaf(em.w, w3, acc[v]);
                    }
                }
            }
            #pragma unroll
            for (int v = 0; v < 4; ++v) {
                const int vv = vb + v;
                if (vv < D_VOCAB)
                    g_tab[(k * D_VOCAB + vv) * D_EMB + e0 + eL] =
                        __float2half(acc[v]);
            }
        }
    }
    __syncthreads();

    // ===== Grid-wide ticket barrier (replay-safe, monotonic) ==============
    if (threadIdx.x == 0) {
        __threadfence();
        unsigned t = atomicAdd(&g_bar, 1u);
        unsigned target = (t / (unsigned)NCTAS) * (unsigned)NCTAS
                          + (unsigned)NCTAS;
        while (*(volatile unsigned*)&g_bar < target) { }
        __threadfence();
    }
    __syncthreads();

    // ===== Phase 2: stage table slice (hot L2) and run main loop ==========
    {
        const char* gb = (const char*)g_tab;
        for (int idx = threadIdx.x; idx < NTAP * D_VOCAB * 8; idx += THREADS) {
            int r = idx >> 3, c = idx & 7;
            s_tab16[idx] = *(const uint4*)(gb + (size_t)r * 256 + g * 128 + c * 16);
        }
    }
    __syncthreads();

    for (int n0 = base + 4 * warp; n0 < end; n0 += step) {
        const int nsel = n0 + q;

        int a[CW];
        if (s2) {
            #pragma unroll
            for (int j = 0; j < 8; ++j) {
                a[2 * j]     = (int)raw[j].x * 8 + l7;
                a[2 * j + 1] = (int)raw[j].z * 8 + l7;
            }
        } else {
            #pragma unroll
            for (int j = 0; j < 4; ++j) {
                a[4 * j]     = (int)raw[j].x * 8 + l7;
                a[4 * j + 1] = (int)raw[j].y * 8 + l7;
                a[4 * j + 2] = (int)raw[j].z * 8 + l7;
                a[4 * j + 3] = (int)raw[j].w * 8 + l7;
            }
        }

        // Prefetch next iteration's ids; latency hides under t-loop.
        {
            const int nn = n0 + step + q;
            const int nc = min(nn < end ? nn : (end - 1), end - 1);
            if (s2) {
                const uint4* p = (const uint4*)(ids_raw + (size_t)nc * 32);
                #pragma unroll
                for (int j = 0; j < 8; ++j) raw[j] = __ldg(&p[j]);
            } else {
                const uint4* p = (const uint4*)(ids_raw + (size_t)nc * 16);
                #pragma unroll
                for (int j = 0; j < 4; ++j) raw[j] = __ldg(&p[j]);
            }
        }

        uint4 me, mo;
        #pragma unroll
        for (int t = 0; t < CW; ++t) {
            const int klo = (t < 2) ? (2 - t) : 0;
            const int khi = (t > CW - 3) ? (CW + 1 - t) : NTAP - 1;

            uint4 s[NTAP];
            #pragma unroll
            for (int k = 0; k < NTAP; ++k) {
                if (k < klo || k > khi) continue;
                s[k] = s_tab16[k * TAPSTRIDE16 + a[t + k - 2]];
            }

            uint4 y;
            const int nv = khi - klo + 1;
            if (nv == 5) {
                y = h2add4(h2add4(h2add4(s[0], s[1]), h2add4(s[2], s[3])), s[4]);
            } else if (nv == 4) {
                y = h2add4(h2add4(s[klo], s[klo + 1]), h2add4(s[klo + 2], s[klo + 3]));
            } else {
                y = h2add4(h2add4(s[klo], s[klo + 1]), s[klo + 2]);
            }

            if (t == 0)      me = y;
            else if (t == 1) mo = y;
            else if ((t & 1) == 0) me = h2max4(me, y);
            else                   mo = h2max4(mo, y);
        }
        const uint4 m = h2max4(me, mo);

        if (nsel < end) {
            const float4 bias0 = __ldg((const float4*)(conv_b + g * 64 + l7 * 8));
            const float4 bias1 = __ldg((const float4*)(conv_b + g * 64 + l7 * 8 + 4));
            float2 c0 = __half22float2(*(const __half2*)&m.x);
            float2 c1 = __half22float2(*(const __half2*)&m.y);
            float2 c2 = __half22float2(*(const __half2*)&m.z);
            float2 c3 = __half22float2(*(const __half2*)&m.w);
            float4 o0, o1;
            o0.x = c0.x + bias0.x; o0.y = c0.y + bias0.y;
            o0.z = c1.x + bias0.z; o0.w = c1.y + bias0.w;
            o1.x = c2.x + bias1.x; o1.y = c2.y + bias1.y;
            o1.z = c3.x + bias1.z; o1.w = c3.y + bias1.w;
            float* op = out + (size_t)nsel * D_EMB + g * 64 + l7 * 8;
            *(float4*)op = o0;
            *(float4*)(op + 4) = o1;
        }
    }
}

// ---------------------------------------------------------------------------
extern "C" void kernel_launch(void* const* d_in, const int* in_sizes, int n_in,
                              void* d_out, int out_size) {
    const int* input = nullptr;
    const float* emb = nullptr;
    const float* conv_w = nullptr;
    const float* conv_b = nullptr;
    for (int i = 0; i < n_in; ++i) {
        switch (in_sizes[i]) {
            case 524288: input  = (const int*)d_in[i];   break;  // ids [128,256,16]
            case 33536:  emb    = (const float*)d_in[i]; break;  // [262,128]
            case 81920:  conv_w = (const float*)d_in[i]; break;  // [128,128,5]
            case 128:    conv_b = (const float*)d_in[i]; break;  // [128]
            default: break;  // lengths (32768) unused
        }
    }

    cudaFuncSetAttribute(conv_char_fused,
                         cudaFuncAttributeMaxDynamicSharedMemorySize, SMEM_BYTES);
    conv_char_fused<<<dim3(NCHUNK, 2), THREADS, SMEM_BYTES>>>(
        input, emb, conv_w, conv_b, (float*)d_out);
}

// round 11
// speedup vs baseline: 1.3444x; 1.0558x over previous
#include <cuda_runtime.h>
#include <cuda_fp16.h>
#include <cstdint>

#define D_VOCAB 262
#define D_EMB   128
#define NTAP    5
#define CW      16
#define NSEQ    32768
#define NCHUNK  74
#define THREADS 512
#define NCTAS   (NCHUNK * 2)            // 148
// smem: table region [NTAP*D_VOCAB] rows of 64 ch (8 x uint4) = 167,680 B
#define SMEM_BYTES (NTAP * D_VOCAB * 32 * 4)
// uint4-unit stride of one tap plane: 262 rows * 8 uint4
#define TAPSTRIDE16 (D_VOCAB * 8)
// phase-1 weight scratch: ws[i][k*32+eL], row stride 164 floats (83,968 B)
#define WROW 164
// phase-1 emb scratch lives right after ws: 8 rows x 128 floats (4 KB)
#define EMB_OFF (D_EMB * WROW)

// fp16 contrib table: [tap][vocab][emb]
__device__ __align__(16) __half g_tab[NTAP * D_VOCAB * D_EMB];
// grid-wide ticket barrier (monotonic across graph replays; no reset needed)
__device__ unsigned g_bar;

// ---------------------------------------------------------------------------
// half2 x4 helpers on uint4-packed fp16
// ---------------------------------------------------------------------------
__device__ __forceinline__ uint4 h2add4(uint4 a, uint4 b) {
    uint4 r;
    *(__half2*)&r.x = __hadd2(*(const __half2*)&a.x, *(const __half2*)&b.x);
    *(__half2*)&r.y = __hadd2(*(const __half2*)&a.y, *(const __half2*)&b.y);
    *(__half2*)&r.z = __hadd2(*(const __half2*)&a.z, *(const __half2*)&b.z);
    *(__half2*)&r.w = __hadd2(*(const __half2*)&a.w, *(const __half2*)&b.w);
    return r;
}
__device__ __forceinline__ uint4 h2max4(uint4 a, uint4 b) {
    uint4 r;
    *(__half2*)&r.x = __hmax2(*(const __half2*)&a.x, *(const __half2*)&b.x);
    *(__half2*)&r.y = __hmax2(*(const __half2*)&a.y, *(const __half2*)&b.y);
    *(__half2*)&r.z = __hmax2(*(const __half2*)&a.z, *(const __half2*)&b.z);
    *(__half2*)&r.w = __hmax2(*(const __half2*)&a.w, *(const __half2*)&b.w);
    return r;
}

// ---------------------------------------------------------------------------
// Fused kernel. Grid (74, 2) = 148 CTAs, 164 KB smem -> 1 CTA/SM, all
// co-resident (GB300 has 152 SMs) -> device-wide ticket barrier is safe.
// Phase 1: CTAs jointly build g_tab[k][v][e]; conv_w e-slice AND the 8 emb
//   rows are staged into smem first, so compute is pure LDS+FMA (no mid-
//   chain LDG latency — the R10 bottleneck).
// Barrier: monotonic ticket barrier (replay-safe under graph capture).
// Phase 2: R5 main loop (measured 27.3-28.5us) — table staged from hot L2.
// ---------------------------------------------------------------------------
__global__ void __launch_bounds__(THREADS, 1)
conv_char_fused(const int* __restrict__ ids_raw,
                const float* __restrict__ emb,
                const float* __restrict__ conv_w,
                const float* __restrict__ conv_b,
                float* __restrict__ out) {
    extern __shared__ uint4 s_tab16[];
    float* ws = (float*)s_tab16;                 // phase-1 alias (88 KB)
    const int g = blockIdx.y;
    const int lane = threadIdx.x & 31;
    const int warp = threadIdx.x >> 5;
    const int l7 = lane & 7;
    const int q = lane >> 3;

    // -- s2 detection + first id prefetch (overlaps phase 1) ---------------
    int s2;
    {
        int v = ids_raw[2 * lane + 1] | ids_raw[64 + 2 * lane + 1];
        s2 = (__ballot_sync(0xffffffffu, v != 0) == 0u) ? 1 : 0;
    }
    const int chunk = (NSEQ + NCHUNK - 1) / NCHUNK;  // 443
    const int base = blockIdx.x * chunk;
    const int end = min(base + chunk, NSEQ);
    const int step = 4 * (THREADS / 32);             // 64

    uint4 raw[8];
    {
        const int nc = min(base + 4 * warp + q, end - 1);
        if (s2) {
            const uint4* p = (const uint4*)(ids_raw + (size_t)nc * 32);
            #pragma unroll
            for (int j = 0; j < 8; ++j) raw[j] = __ldg(&p[j]);
        } else {
            const uint4* p = (const uint4*)(ids_raw + (size_t)nc * 16);
            #pragma unroll
            for (int j = 0; j < 4; ++j) raw[j] = __ldg(&p[j]);
        }
    }

    // ===== Phase 1: build this CTA's slice of g_tab =======================
    {
        const int cta = blockIdx.y * NCHUNK + blockIdx.x;   // 0..147
        const int eg = cta & 3;            // 32-e group
        const int vg = cta >> 2;           // 8-v group (>=33 -> idle)
        const int e0 = eg * 32;
        const int v0 = vg * 8;

        // Stage conv_w rows e0..e0+31 transposed: ws[i*WROW + k*32 + r].
        const float4* __restrict__ cw4 = (const float4*)conv_w;
        for (int idx = threadIdx.x; idx < 32 * 160; idx += THREADS) {
            const int r = idx / 160;
            const int c = idx % 160;
            float4 w = __ldg(&cw4[(size_t)(e0 + r) * 160 + c]);
            const int j = 4 * c;
            ws[((j + 0) / 5) * WROW + ((j + 0) % 5) * 32 + r] = w.x;
            ws[((j + 1) / 5) * WROW + ((j + 1) % 5) * 32 + r] = w.y;
            ws[((j + 2) / 5) * WROW + ((j + 2) % 5) * 32 + r] = w.z;
            ws[((j + 3) / 5) * WROW + ((j + 3) % 5) * 32 + r] = w.w;
        }
        // Stage the 8 emb rows this CTA needs (4 KB): 256 float4.
        {
            const float4* __restrict__ embg = (const float4*)emb;
            float4* se4 = (float4*)(ws + EMB_OFF);
            if (threadIdx.x < 256) {
                const int vr = threadIdx.x >> 5;     // 0..7
                const int c = threadIdx.x & 31;
                const int vv = v0 + vr;
                se4[threadIdx.x] = (vv < D_VOCAB)
                    ? __ldg(&embg[vv * 32 + c])
                    : make_float4(0.f, 0.f, 0.f, 0.f);
            }
        }
        __syncthreads();

        if (threadIdx.x < 320 && v0 < D_VOCAB) {
            const int vh = threadIdx.x / 160;          // 0..1
            const int k = (threadIdx.x % 160) >> 5;    // 0..4
            const int eL = threadIdx.x & 31;
            const float* __restrict__ wcol = ws + k * 32 + eL;
            const float4* __restrict__ se4 = (const float4*)(ws + EMB_OFF);
            const int vb = vh * 4;                     // local vocab base

            float acc[4];
            #pragma unroll
            for (int v = 0; v < 4; ++v) acc[v] = 0.f;

            #pragma unroll 4
            for (int i4 = 0; i4 < 32; ++i4) {
                const float w0 = wcol[(i4 * 4 + 0) * WROW];
                const float w1 = wcol[(i4 * 4 + 1) * WROW];
                const float w2 = wcol[(i4 * 4 + 2) * WROW];
                const float w3 = wcol[(i4 * 4 + 3) * WROW];
                #pragma unroll
                for (int v = 0; v < 4; ++v) {
                    float4 em = se4[(vb + v) * 32 + i4];   // smem broadcast
                    acc[v] = fmaf(em.x, w0, acc[v]);
                    acc[v] = fmaf(em.y, w1, acc[v]);
                    acc[v] = fmaf(em.z, w2, acc[v]);
                    acc[v] = fmaf(em.w, w3, acc[v]);
                }
            }
            #pragma unroll
            for (int v = 0; v < 4; ++v) {
                const int vv = v0 + vb + v;
                if (vv < D_VOCAB)
                    g_tab[(k * D_VOCAB + vv) * D_EMB + e0 + eL] =
                        __float2half(acc[v]);
            }
        }
    }
    // Release all lanes' g_tab stores, then grid barrier.
    __threadfence();
    __syncthreads();

    if (threadIdx.x == 0) {
        unsigned t = atomicAdd(&g_bar, 1u);
        unsigned target = (t / (unsigned)NCTAS) * (unsigned)NCTAS
                          + (unsigned)NCTAS;
        while (*(volatile unsigned*)&g_bar < target) { }
        __threadfence();
    }
    __syncthreads();

    // ===== Phase 2: stage table slice (hot L2) and run main loop ==========
    {
        const char* gb = (const char*)g_tab;
        for (int idx = threadIdx.x; idx < NTAP * D_VOCAB * 8; idx += THREADS) {
            int r = idx >> 3, c = idx & 7;
            s_tab16[idx] = *(const uint4*)(gb + (size_t)r * 256 + g * 128 + c * 16);
        }
    }
    __syncthreads();

    for (int n0 = base + 4 * warp; n0 < end; n0 += step) {
        const int nsel = n0 + q;

        int a[CW];
        if (s2) {
            #pragma unroll
            for (int j = 0; j < 8; ++j) {
                a[2 * j]     = (int)raw[j].x * 8 + l7;
                a[2 * j + 1] = (int)raw[j].z * 8 + l7;
            }
        } else {
            #pragma unroll
            for (int j = 0; j < 4; ++j) {
                a[4 * j]     = (int)raw[j].x * 8 + l7;
                a[4 * j + 1] = (int)raw[j].y * 8 + l7;
                a[4 * j + 2] = (int)raw[j].z * 8 + l7;
                a[4 * j + 3] = (int)raw[j].w * 8 + l7;
            }
        }

        // Prefetch next iteration's ids; latency hides under t-loop.
        {
            const int nn = n0 + step + q;
            const int nc = min(nn < end ? nn : (end - 1), end - 1);
            if (s2) {
                const uint4* p = (const uint4*)(ids_raw + (size_t)nc * 32);
                #pragma unroll
                for (int j = 0; j < 8; ++j) raw[j] = __ldg(&p[j]);
            } else {
                const uint4* p = (const uint4*)(ids_raw + (size_t)nc * 16);
                #pragma unroll
                for (int j = 0; j < 4; ++j) raw[j] = __ldg(&p[j]);
            }
        }

        uint4 me, mo;
        #pragma unroll
        for (int t = 0; t < CW; ++t) {
            const int klo = (t < 2) ? (2 - t) : 0;
            const int khi = (t > CW - 3) ? (CW + 1 - t) : NTAP - 1;

            uint4 s[NTAP];
            #pragma unroll
            for (int k = 0; k < NTAP; ++k) {
                if (k < klo || k > khi) continue;
                s[k] = s_tab16[k * TAPSTRIDE16 + a[t + k - 2]];
            }

            uint4 y;
            const int nv = khi - klo + 1;
            if (nv == 5) {
                y = h2add4(h2add4(h2add4(s[0], s[1]), h2add4(s[2], s[3])), s[4]);
            } else if (nv == 4) {
                y = h2add4(h2add4(s[klo], s[klo + 1]), h2add4(s[klo + 2], s[klo + 3]));
            } else {
                y = h2add4(h2add4(s[klo], s[klo + 1]), s[klo + 2]);
            }

            if (t == 0)      me = y;
            else if (t == 1) mo = y;
            else if ((t & 1) == 0) me = h2max4(me, y);
            else                   mo = h2max4(mo, y);
        }
        const uint4 m = h2max4(me, mo);

        if (nsel < end) {
            const float4 bias0 = __ldg((const float4*)(conv_b + g * 64 + l7 * 8));
            const float4 bias1 = __ldg((const float4*)(conv_b + g * 64 + l7 * 8 + 4));
            float2 c0 = __half22float2(*(const __half2*)&m.x);
            float2 c1 = __half22float2(*(const __half2*)&m.y);
            float2 c2 = __half22float2(*(const __half2*)&m.z);
            float2 c3 = __half22float2(*(const __half2*)&m.w);
            float4 o0, o1;
            o0.x = c0.x + bias0.x; o0.y = c0.y + bias0.y;
            o0.z = c1.x + bias0.z; o0.w = c1.y + bias0.w;
            o1.x = c2.x + bias1.x; o1.y = c2.y + bias1.y;
            o1.z = c3.x + bias1.z; o1.w = c3.y + bias1.w;
            float* op = out + (size_t)nsel * D_EMB + g * 64 + l7 * 8;
            *(float4*)op = o0;
            *(float4*)(op + 4) = o1;
        }
    }
}

// ---------------------------------------------------------------------------
extern "C" void kernel_launch(void* const* d_in, const int* in_sizes, int n_in,
                              void* d_out, int out_size) {
    const int* input = nullptr;
    const float* emb = nullptr;
    const float* conv_w = nullptr;
    const float* conv_b = nullptr;
    for (int i = 0; i < n_in; ++i) {
        switch (in_sizes[i]) {
            case 524288: input  = (const int*)d_in[i];   break;  // ids [128,256,16]
            case 33536:  emb    = (const float*)d_in[i]; break;  // [262,128]
            case 81920:  conv_w = (const float*)d_in[i]; break;  // [128,128,5]
            case 128:    conv_b = (const float*)d_in[i]; break;  // [128]
            default: break;  // lengths (32768) unused
        }
    }

    cudaFuncSetAttribute(conv_char_fused,
                         cudaFuncAttributeMaxDynamicSharedMemorySize, SMEM_BYTES);
    conv_char_fused<<<dim3(NCHUNK, 2), THREADS, SMEM_BYTES>>>(
        input, emb, conv_w, conv_b, (float*)d_out);
}

// round 13
// speedup vs baseline: 1.3542x; 1.0072x over previous
#include <cuda_runtime.h>
#include <cuda_fp16.h>
#include <cstdint>

#define D_VOCAB 262
#define D_EMB   128
#define NTAP    5
#define CW      16
#define NSEQ    32768
#define NCHUNK  74
#define THREADS 640
#define NCTAS   (NCHUNK * 2)            // 148
// smem: table region [NTAP*D_VOCAB] rows of 64 ch (8 x uint4) = 167,680 B
#define SMEM_BYTES (NTAP * D_VOCAB * 32 * 4)
// uint4-unit stride of one tap plane: 262 rows * 8 uint4
#define TAPSTRIDE16 (D_VOCAB * 8)
// phase-1 weight scratch: ws[i][k*32+eL], row stride 164 floats (83,968 B)
#define WROW 164
// phase-1 emb scratch right after ws: 8 rows x 128 floats (4 KB)
#define EMB_OFF (D_EMB * WROW)

// fp16 contrib table: [tap][vocab][emb]
__device__ __align__(16) __half g_tab[NTAP * D_VOCAB * D_EMB];
// narrowed int16 ids (written phase 1, read phase 2 — PLAIN loads only;
// __ldg here is illegal: data is written within this kernel launch)
__device__ __align__(16) unsigned short g_ids16[NSEQ * CW];
// grid-wide ticket barrier (monotonic across graph replays; no reset needed)
__device__ unsigned g_bar;

// ---------------------------------------------------------------------------
// half2 x4 helpers on uint4-packed fp16
// ---------------------------------------------------------------------------
__device__ __forceinline__ uint4 h2add4(uint4 a, uint4 b) {
    uint4 r;
    *(__half2*)&r.x = __hadd2(*(const __half2*)&a.x, *(const __half2*)&b.x);
    *(__half2*)&r.y = __hadd2(*(const __half2*)&a.y, *(const __half2*)&b.y);
    *(__half2*)&r.z = __hadd2(*(const __half2*)&a.z, *(const __half2*)&b.z);
    *(__half2*)&r.w = __hadd2(*(const __half2*)&a.w, *(const __half2*)&b.w);
    return r;
}
__device__ __forceinline__ uint4 h2max4(uint4 a, uint4 b) {
    uint4 r;
    *(__half2*)&r.x = __hmax2(*(const __half2*)&a.x, *(const __half2*)&b.x);
    *(__half2*)&r.y = __hmax2(*(const __half2*)&a.y, *(const __half2*)&b.y);
    *(__half2*)&r.z = __hmax2(*(const __half2*)&a.z, *(const __half2*)&b.z);
    *(__half2*)&r.w = __hmax2(*(const __half2*)&a.w, *(const __half2*)&b.w);
    return r;
}

// ---------------------------------------------------------------------------
// Fused kernel. Grid (74, 2) = 148 CTAs, 164 KB smem -> 1 CTA/SM, all
// co-resident -> device-wide ticket barrier is safe.
// Phase 1: (a) CTAs jointly build g_tab (conv_w slice + 8 emb rows staged in
//   smem, all 640 threads compute); (b) ids narrowed to int16 in g_ids16.
// Barrier: monotonic ticket barrier (replay-safe).
// Phase 2: main loop at 640 threads / 20 warps, enabled by the int16 id path
//   (raw2[2] = 8 regs, branch-free). All g_ids16 reads are coherent plain
//   loads — same pattern as the proven g_tab cross-phase reads.
// ---------------------------------------------------------------------------
__global__ void __launch_bounds__(THREADS, 1)
conv_char_fused(const int* __restrict__ ids_raw,
                const float* __restrict__ emb,
                const float* __restrict__ conv_w,
                const float* __restrict__ conv_b,
                float* __restrict__ out) {
    extern __shared__ uint4 s_tab16[];
    float* ws = (float*)s_tab16;                 // phase-1 alias (88 KB)
    const int g = blockIdx.y;
    const int lane = threadIdx.x & 31;
    const int warp = threadIdx.x >> 5;
    const int l7 = lane & 7;
    const int q = lane >> 3;
    const int cta = blockIdx.y * NCHUNK + blockIdx.x;   // 0..147

    // Per-warp int64-vs-int32 detection (int64 ids < 262 -> zero high words).
    int s2;
    {
        int v = ids_raw[2 * lane + 1] | ids_raw[64 + 2 * lane + 1];
        s2 = (__ballot_sync(0xffffffffu, v != 0) == 0u) ? 1 : 0;
    }

    // ===== Phase 1a: build this CTA's slice of g_tab ======================
    {
        const int eg = cta & 3;            // 32-e group
        const int vg = cta >> 2;           // 8-v group (>=33 -> idle)
        const int e0 = eg * 32;
        const int v0 = vg * 8;

        // Stage conv_w rows e0..e0+31 transposed: ws[i*WROW + k*32 + r].
        const float4* __restrict__ cw4 = (const float4*)conv_w;
        for (int idx = threadIdx.x; idx < 32 * 160; idx += THREADS) {
            const int r = idx / 160;
            const int c = idx % 160;
            float4 w = __ldg(&cw4[(size_t)(e0 + r) * 160 + c]);
            const int j = 4 * c;
            ws[((j + 0) / 5) * WROW + ((j + 0) % 5) * 32 + r] = w.x;
            ws[((j + 1) / 5) * WROW + ((j + 1) % 5) * 32 + r] = w.y;
            ws[((j + 2) / 5) * WROW + ((j + 2) % 5) * 32 + r] = w.z;
            ws[((j + 3) / 5) * WROW + ((j + 3) % 5) * 32 + r] = w.w;
        }
        // Stage the 8 emb rows this CTA needs (4 KB): 256 float4.
        {
            const float4* __restrict__ embg = (const float4*)emb;
            float4* se4 = (float4*)(ws + EMB_OFF);
            if (threadIdx.x < 256) {
                const int vr = threadIdx.x >> 5;     // 0..7
                const int c = threadIdx.x & 31;
                const int vv = v0 + vr;
                se4[threadIdx.x] = (vv < D_VOCAB)
                    ? __ldg(&embg[vv * 32 + c])
                    : make_float4(0.f, 0.f, 0.f, 0.f);
            }
        }
        __syncthreads();

        if (v0 < D_VOCAB) {
            // 640 threads = (vh 0..3) x (k 0..4) x (eL 0..31); 2 v each.
            const int vh = threadIdx.x / 160;
            const int k = (threadIdx.x % 160) >> 5;
            const int eL = threadIdx.x & 31;
            const float* __restrict__ wcol = ws + k * 32 + eL;
            const float4* __restrict__ se4 = (const float4*)(ws + EMB_OFF);
            const int vb = vh * 2;                   // local vocab base

            float acc0 = 0.f, acc1 = 0.f;
            #pragma unroll 4
            for (int i4 = 0; i4 < 32; ++i4) {
                const float w0 = wcol[(i4 * 4 + 0) * WROW];
                const float w1 = wcol[(i4 * 4 + 1) * WROW];
                const float w2 = wcol[(i4 * 4 + 2) * WROW];
                const float w3 = wcol[(i4 * 4 + 3) * WROW];
                float4 e0v = se4[(vb + 0) * 32 + i4];
                float4 e1v = se4[(vb + 1) * 32 + i4];
                acc0 = fmaf(e0v.x, w0, acc0); acc1 = fmaf(e1v.x, w0, acc1);
                acc0 = fmaf(e0v.y, w1, acc0); acc1 = fmaf(e1v.y, w1, acc1);
                acc0 = fmaf(e0v.z, w2, acc0); acc1 = fmaf(e1v.z, w2, acc1);
                acc0 = fmaf(e0v.w, w3, acc0); acc1 = fmaf(e1v.w, w3, acc1);
            }
            const int vva = v0 + vb, vvb = v0 + vb + 1;
            if (vva < D_VOCAB)
                g_tab[(k * D_VOCAB + vva) * D_EMB + e0 + eL] = __float2half(acc0);
            if (vvb < D_VOCAB)
                g_tab[(k * D_VOCAB + vvb) * D_EMB + e0 + eL] = __float2half(acc1);
        }
    }

    // ===== Phase 1b: narrow ids to int16 (coalesced grid-stride) ==========
    {
        const int stride = NCTAS * THREADS;          // 94720
        int i = cta * THREADS + threadIdx.x;
        if (s2) {
            const uint2* __restrict__ p2 = (const uint2*)ids_raw;
            for (; i < NSEQ * CW; i += stride)
                g_ids16[i] = (unsigned short)__ldg(&p2[i]).x;
        } else {
            for (; i < NSEQ * CW; i += stride)
                g_ids16[i] = (unsigned short)__ldg(&ids_raw[i]);
        }
    }

    // Release all stores, then grid barrier.
    __threadfence();
    __syncthreads();
    if (threadIdx.x == 0) {
        unsigned t = atomicAdd(&g_bar, 1u);
        unsigned target = (t / (unsigned)NCTAS) * (unsigned)NCTAS
                          + (unsigned)NCTAS;
        while (*(volatile unsigned*)&g_bar < target) { }
        __threadfence();
    }
    __syncthreads();

    // ===== Phase 2: main loop =============================================
    const int chunk = (NSEQ + NCHUNK - 1) / NCHUNK;  // 443
    const int base = blockIdx.x * chunk;
    const int end = min(base + chunk, NSEQ);
    const int step = 4 * (THREADS / 32);             // 80

    // Prefetch first iteration's ids (L2-hot). PLAIN coherent loads.
    uint4 raw2[2];
    {
        const int nc = min(base + 4 * warp + q, end - 1);
        const uint4* p = (const uint4*)(g_ids16 + (size_t)nc * CW);
        raw2[0] = p[0];
        raw2[1] = p[1];
    }

    // Stage table slice from hot L2 (10480 x 16 B, coalesced; plain loads).
    {
        const char* gb = (const char*)g_tab;
        for (int idx = threadIdx.x; idx < NTAP * D_VOCAB * 8; idx += THREADS) {
            int r = idx >> 3, c = idx & 7;
            s_tab16[idx] = *(const uint4*)(gb + (size_t)r * 256 + g * 128 + c * 16);
        }
    }
    __syncthreads();

    for (int n0 = base + 4 * warp; n0 < end; n0 += step) {
        const int nsel = n0 + q;

        // Unpack 16 int16 ids -> gather indices a[c] = id*8 + l7.
        int a[CW];
        {
            unsigned w;
            w = raw2[0].x; a[0] = (int)(w & 0xFFFFu) * 8 + l7; a[1] = (int)(w >> 16) * 8 + l7;
            w = raw2[0].y; a[2] = (int)(w & 0xFFFFu) * 8 + l7; a[3] = (int)(w >> 16) * 8 + l7;
            w = raw2[0].z; a[4] = (int)(w & 0xFFFFu) * 8 + l7; a[5] = (int)(w >> 16) * 8 + l7;
            w = raw2[0].w; a[6] = (int)(w & 0xFFFFu) * 8 + l7; a[7] = (int)(w >> 16) * 8 + l7;
            w = raw2[1].x; a[8] = (int)(w & 0xFFFFu) * 8 + l7; a[9] = (int)(w >> 16) * 8 + l7;
            w = raw2[1].y; a[10] = (int)(w & 0xFFFFu) * 8 + l7; a[11] = (int)(w >> 16) * 8 + l7;
            w = raw2[1].z; a[12] = (int)(w & 0xFFFFu) * 8 + l7; a[13] = (int)(w >> 16) * 8 + l7;
            w = raw2[1].w; a[14] = (int)(w & 0xFFFFu) * 8 + l7; a[15] = (int)(w >> 16) * 8 + l7;
        }

        // Prefetch next iteration's ids (plain loads); hides under t-loop.
        {
            const int nn = n0 + step + q;
            const int nc = min(nn < end ? nn : (end - 1), end - 1);
            const uint4* p = (const uint4*)(g_ids16 + (size_t)nc * CW);
            raw2[0] = p[0];
            raw2[1] = p[1];
        }

        // Even/odd-t max chains on 8 channels (4 half2) per lane.
        uint4 me, mo;
        #pragma unroll
        for (int t = 0; t < CW; ++t) {
            const int klo = (t < 2) ? (2 - t) : 0;
            const int khi = (t > CW - 3) ? (CW + 1 - t) : NTAP - 1;

            uint4 s[NTAP];
            #pragma unroll
            for (int k = 0; k < NTAP; ++k) {
                if (k < klo || k > khi) continue;
                s[k] = s_tab16[k * TAPSTRIDE16 + a[t + k - 2]];
            }

            uint4 y;
            const int nv = khi - klo + 1;
            if (nv == 5) {
                y = h2add4(h2add4(h2add4(s[0], s[1]), h2add4(s[2], s[3])), s[4]);
            } else if (nv == 4) {
                y = h2add4(h2add4(s[klo], s[klo + 1]), h2add4(s[klo + 2], s[klo + 3]));
            } else {
                y = h2add4(h2add4(s[klo], s[klo + 1]), s[klo + 2]);
            }

            if (t == 0)      me = y;
            else if (t == 1) mo = y;
            else if ((t & 1) == 0) me = h2max4(me, y);
            else                   mo = h2max4(mo, y);
        }
        const uint4 m = h2max4(me, mo);

        if (nsel < end) {
            const float4 bias0 = __ldg((const float4*)(conv_b + g * 64 + l7 * 8));
            const float4 bias1 = __ldg((const float4*)(conv_b + g * 64 + l7 * 8 + 4));
            float2 c0 = __half22float2(*(const __half2*)&m.x);
            float2 c1 = __half22float2(*(const __half2*)&m.y);
            float2 c2 = __half22float2(*(const __half2*)&m.z);
            float2 c3 = __half22float2(*(const __half2*)&m.w);
            float4 o0, o1;
            o0.x = c0.x + bias0.x; o0.y = c0.y + bias0.y;
            o0.z = c1.x + bias0.z; o0.w = c1.y + bias0.w;
            o1.x = c2.x + bias1.x; o1.y = c2.y + bias1.y;
            o1.z = c3.x + bias1.z; o1.w = c3.y + bias1.w;
            float* op = out + (size_t)nsel * D_EMB + g * 64 + l7 * 8;
            *(float4*)op = o0;
            *(float4*)(op + 4) = o1;
        }
    }
}

// ---------------------------------------------------------------------------
extern "C" void kernel_launch(void* const* d_in, const int* in_sizes, int n_in,
                              void* d_out, int out_size) {
    const int* input = nullptr;
    const float* emb = nullptr;
    const float* conv_w = nullptr;
    const float* conv_b = nullptr;
    for (int i = 0; i < n_in; ++i) {
        switch (in_sizes[i]) {
            case 524288: input  = (const int*)d_in[i];   break;  // ids [128,256,16]
            case 33536:  emb    = (const float*)d_in[i]; break;  // [262,128]
            case 81920:  conv_w = (const float*)d_in[i]; break;  // [128,128,5]
            case 128:    conv_b = (const float*)d_in[i]; break;  // [128]
            default: break;  // lengths (32768) unused
        }
    }

    cudaFuncSetAttribute(conv_char_fused,
                         cudaFuncAttributeMaxDynamicSharedMemorySize, SMEM_BYTES);
    conv_char_fused<<<dim3(NCHUNK, 2), THREADS, SMEM_BYTES>>>(
        input, emb, conv_w, conv_b, (float*)d_out);
}

// round 14
// speedup vs baseline: 1.3690x; 1.0110x over previous
#include <cuda_runtime.h>
#include <cuda_fp16.h>
#include <cstdint>

#define D_VOCAB 262
#define D_EMB   128
#define NTAP    5
#define CW      16
#define NSEQ    32768
#define NCHUNK  74
#define THREADS 512
#define NCTAS   (NCHUNK * 2)            // 148
// smem: table region [NTAP*D_VOCAB] rows of 64 ch (8 x uint4) = 167,680 B
#define SMEM_BYTES (NTAP * D_VOCAB * 32 * 4)
// uint4-unit stride of one tap plane: 262 rows * 8 uint4
#define TAPSTRIDE16 (D_VOCAB * 8)
// phase-1 weight scratch: ws[i][k*32+eL], row stride 164 floats (83,968 B)
#define WROW 164
// phase-1 emb scratch right after ws: 8 rows x 128 floats (4 KB)
#define EMB_OFF (D_EMB * WROW)

// fp16 contrib table: [tap][vocab][emb]
__device__ __align__(16) __half g_tab[NTAP * D_VOCAB * D_EMB];
// narrowed int16 ids (written phase 1, read phase 2 — PLAIN loads only;
// __ldg is illegal here: written within this launch, RO-path is incoherent)
__device__ __align__(16) unsigned short g_ids16[NSEQ * CW];
// grid-wide ticket barrier (monotonic across graph replays; no reset needed)
__device__ unsigned g_bar;

// ---------------------------------------------------------------------------
// half2 x4 helpers on uint4-packed fp16
// ---------------------------------------------------------------------------
__device__ __forceinline__ uint4 h2add4(uint4 a, uint4 b) {
    uint4 r;
    *(__half2*)&r.x = __hadd2(*(const __half2*)&a.x, *(const __half2*)&b.x);
    *(__half2*)&r.y = __hadd2(*(const __half2*)&a.y, *(const __half2*)&b.y);
    *(__half2*)&r.z = __hadd2(*(const __half2*)&a.z, *(const __half2*)&b.z);
    *(__half2*)&r.w = __hadd2(*(const __half2*)&a.w, *(const __half2*)&b.w);
    return r;
}
__device__ __forceinline__ uint4 h2max4(uint4 a, uint4 b) {
    uint4 r;
    *(__half2*)&r.x = __hmax2(*(const __half2*)&a.x, *(const __half2*)&b.x);
    *(__half2*)&r.y = __hmax2(*(const __half2*)&a.y, *(const __half2*)&b.y);
    *(__half2*)&r.z = __hmax2(*(const __half2*)&a.z, *(const __half2*)&b.z);
    *(__half2*)&r.w = __hmax2(*(const __half2*)&a.w, *(const __half2*)&b.w);
    return r;
}

// ---------------------------------------------------------------------------
// Fused kernel. Grid (74, 2) = 148 CTAs, 164 KB smem -> 1 CTA/SM, all
// co-resident -> device-wide ticket barrier is safe.
// Phase 1: (a) build g_tab (conv_w slice + emb rows staged in smem);
//          (b) narrow ids to int16 in g_ids16 (coalesced grid-stride).
// Barrier: monotonic ticket barrier (replay-safe).
// Phase 2: 512 threads, int16 id path, and an EXPLICIT double-buffered
//   software pipeline over t: iteration t issues all of t+1's gathers
//   before t's adds, forcing 4-5 LDS in flight per warp (attacks the
//   measured L1=65% bubble; floor is ~18.9us of crossbar time).
// ---------------------------------------------------------------------------
__global__ void __launch_bounds__(THREADS, 1)
conv_char_fused(const int* __restrict__ ids_raw,
                const float* __restrict__ emb,
                const float* __restrict__ conv_w,
                const float* __restrict__ conv_b,
                float* __restrict__ out) {
    extern __shared__ uint4 s_tab16[];
    float* ws = (float*)s_tab16;                 // phase-1 alias (88 KB)
    const int g = blockIdx.y;
    const int lane = threadIdx.x & 31;
    const int warp = threadIdx.x >> 5;
    const int l7 = lane & 7;
    const int q = lane >> 3;
    const int cta = blockIdx.y * NCHUNK + blockIdx.x;   // 0..147

    // Per-warp int64-vs-int32 detection (int64 ids < 262 -> zero high words).
    int s2;
    {
        int v = ids_raw[2 * lane + 1] | ids_raw[64 + 2 * lane + 1];
        s2 = (__ballot_sync(0xffffffffu, v != 0) == 0u) ? 1 : 0;
    }

    // ===== Phase 1a: build this CTA's slice of g_tab ======================
    {
        const int eg = cta & 3;            // 32-e group
        const int vg = cta >> 2;           // 8-v group (>=33 -> idle)
        const int e0 = eg * 32;
        const int v0 = vg * 8;

        // Stage conv_w rows e0..e0+31 transposed: ws[i*WROW + k*32 + r].
        const float4* __restrict__ cw4 = (const float4*)conv_w;
        for (int idx = threadIdx.x; idx < 32 * 160; idx += THREADS) {
            const int r = idx / 160;
            const int c = idx % 160;
            float4 w = __ldg(&cw4[(size_t)(e0 + r) * 160 + c]);
            const int j = 4 * c;
            ws[((j + 0) / 5) * WROW + ((j + 0) % 5) * 32 + r] = w.x;
            ws[((j + 1) / 5) * WROW + ((j + 1) % 5) * 32 + r] = w.y;
            ws[((j + 2) / 5) * WROW + ((j + 2) % 5) * 32 + r] = w.z;
            ws[((j + 3) / 5) * WROW + ((j + 3) % 5) * 32 + r] = w.w;
        }
        // Stage the 8 emb rows this CTA needs (4 KB): 256 float4.
        {
            const float4* __restrict__ embg = (const float4*)emb;
            float4* se4 = (float4*)(ws + EMB_OFF);
            if (threadIdx.x < 256) {
                const int vr = threadIdx.x >> 5;     // 0..7
                const int c = threadIdx.x & 31;
                const int vv = v0 + vr;
                se4[threadIdx.x] = (vv < D_VOCAB)
                    ? __ldg(&embg[vv * 32 + c])
                    : make_float4(0.f, 0.f, 0.f, 0.f);
            }
        }
        __syncthreads();

        if (threadIdx.x < 320 && v0 < D_VOCAB) {
            const int vh = threadIdx.x / 160;          // 0..1
            const int k = (threadIdx.x % 160) >> 5;    // 0..4
            const int eL = threadIdx.x & 31;
            const float* __restrict__ wcol = ws + k * 32 + eL;
            const float4* __restrict__ se4 = (const float4*)(ws + EMB_OFF);
            const int vb = vh * 4;                     // local vocab base

            float acc[4];
            #pragma unroll
            for (int v = 0; v < 4; ++v) acc[v] = 0.f;

            #pragma unroll 4
            for (int i4 = 0; i4 < 32; ++i4) {
                const float w0 = wcol[(i4 * 4 + 0) * WROW];
                const float w1 = wcol[(i4 * 4 + 1) * WROW];
                const float w2 = wcol[(i4 * 4 + 2) * WROW];
                const float w3 = wcol[(i4 * 4 + 3) * WROW];
                #pragma unroll
                for (int v = 0; v < 4; ++v) {
                    float4 em = se4[(vb + v) * 32 + i4];   // smem broadcast
                    acc[v] = fmaf(em.x, w0, acc[v]);
                    acc[v] = fmaf(em.y, w1, acc[v]);
                    acc[v] = fmaf(em.z, w2, acc[v]);
                    acc[v] = fmaf(em.w, w3, acc[v]);
                }
            }
            #pragma unroll
            for (int v = 0; v < 4; ++v) {
                const int vv = v0 + vb + v;
                if (vv < D_VOCAB)
                    g_tab[(k * D_VOCAB + vv) * D_EMB + e0 + eL] =
                        __float2half(acc[v]);
            }
        }
    }

    // ===== Phase 1b: narrow ids to int16 (coalesced grid-stride) ==========
    {
        const int stride = NCTAS * THREADS;
        int i = cta * THREADS + threadIdx.x;
        if (s2) {
            const uint2* __restrict__ p2 = (const uint2*)ids_raw;
            for (; i < NSEQ * CW; i += stride)
                g_ids16[i] = (unsigned short)__ldg(&p2[i]).x;
        } else {
            for (; i < NSEQ * CW; i += stride)
                g_ids16[i] = (unsigned short)__ldg(&ids_raw[i]);
        }
    }

    // Release all stores, then grid barrier.
    __threadfence();
    __syncthreads();
    if (threadIdx.x == 0) {
        unsigned t = atomicAdd(&g_bar, 1u);
        unsigned target = (t / (unsigned)NCTAS) * (unsigned)NCTAS
                          + (unsigned)NCTAS;
        while (*(volatile unsigned*)&g_bar < target) { }
        __threadfence();
    }
    __syncthreads();

    // ===== Phase 2: main loop =============================================
    const int chunk = (NSEQ + NCHUNK - 1) / NCHUNK;  // 443
    const int base = blockIdx.x * chunk;
    const int end = min(base + chunk, NSEQ);
    const int step = 4 * (THREADS / 32);             // 64

    // Prefetch first iteration's ids (L2-hot). PLAIN coherent loads.
    uint4 raw2[2];
    {
        const int nc = min(base + 4 * warp + q, end - 1);
        const uint4* p = (const uint4*)(g_ids16 + (size_t)nc * CW);
        raw2[0] = p[0];
        raw2[1] = p[1];
    }

    // Stage table slice from hot L2 (10480 x 16 B, coalesced; plain loads).
    {
        const char* gb = (const char*)g_tab;
        for (int idx = threadIdx.x; idx < NTAP * D_VOCAB * 8; idx += THREADS) {
            int r = idx >> 3, c = idx & 7;
            s_tab16[idx] = *(const uint4*)(gb + (size_t)r * 256 + g * 128 + c * 16);
        }
    }
    __syncthreads();

    for (int n0 = base + 4 * warp; n0 < end; n0 += step) {
        const int nsel = n0 + q;

        // Unpack 16 int16 ids -> gather indices a[c] = id*8 + l7.
        int a[CW];
        {
            unsigned w;
            w = raw2[0].x; a[0] = (int)(w & 0xFFFFu) * 8 + l7; a[1] = (int)(w >> 16) * 8 + l7;
            w = raw2[0].y; a[2] = (int)(w & 0xFFFFu) * 8 + l7; a[3] = (int)(w >> 16) * 8 + l7;
            w = raw2[0].z; a[4] = (int)(w & 0xFFFFu) * 8 + l7; a[5] = (int)(w >> 16) * 8 + l7;
            w = raw2[0].w; a[6] = (int)(w & 0xFFFFu) * 8 + l7; a[7] = (int)(w >> 16) * 8 + l7;
            w = raw2[1].x; a[8] = (int)(w & 0xFFFFu) * 8 + l7; a[9] = (int)(w >> 16) * 8 + l7;
            w = raw2[1].y; a[10] = (int)(w & 0xFFFFu) * 8 + l7; a[11] = (int)(w >> 16) * 8 + l7;
            w = raw2[1].z; a[12] = (int)(w & 0xFFFFu) * 8 + l7; a[13] = (int)(w >> 16) * 8 + l7;
            w = raw2[1].w; a[14] = (int)(w & 0xFFFFu) * 8 + l7; a[15] = (int)(w >> 16) * 8 + l7;
        }

        // Prefetch next iteration's ids (plain loads); hides under t-loop.
        {
            const int nn = n0 + step + q;
            const int nc = min(nn < end ? nn : (end - 1), end - 1);
            const uint4* p = (const uint4*)(g_ids16 + (size_t)nc * CW);
            raw2[0] = p[0];
            raw2[1] = p[1];
        }

        // Explicit double-buffered pipeline over t: t+1's gathers are
        // issued BEFORE t's adds consume buffer cur.
        uint4 sb[2][NTAP];
        {   // preload t=0 (valid k: 2..4)
            #pragma unroll
            for (int k = 2; k < NTAP; ++k)
                sb[0][k] = s_tab16[k * TAPSTRIDE16 + a[k - 2]];
        }

        uint4 me, mo;
        #pragma unroll
        for (int t = 0; t < CW; ++t) {
            const int cur = t & 1;
            const int nxt = cur ^ 1;

            if (t + 1 < CW) {   // issue t+1's gathers now
                const int tn = t + 1;
                const int klo_n = (tn < 2) ? (2 - tn) : 0;
                const int khi_n = (tn > CW - 3) ? (CW + 1 - tn) : NTAP - 1;
                #pragma unroll
                for (int k = 0; k < NTAP; ++k) {
                    if (k < klo_n || k > khi_n) continue;
                    sb[nxt][k] = s_tab16[k * TAPSTRIDE16 + a[tn + k - 2]];
                }
            }

            const int klo = (t < 2) ? (2 - t) : 0;
            const int khi = (t > CW - 3) ? (CW + 1 - t) : NTAP - 1;
            const int nv = khi - klo + 1;

            uint4 y;
            if (nv == 5) {
                y = h2add4(h2add4(h2add4(sb[cur][0], sb[cur][1]),
                                  h2add4(sb[cur][2], sb[cur][3])), sb[cur][4]);
            } else if (nv == 4) {
                y = h2add4(h2add4(sb[cur][klo], sb[cur][klo + 1]),
                           h2add4(sb[cur][klo + 2], sb[cur][klo + 3]));
            } else {
                y = h2add4(h2add4(sb[cur][klo], sb[cur][klo + 1]),
                           sb[cur][klo + 2]);
            }

            if (t == 0)      me = y;
            else if (t == 1) mo = y;
            else if ((t & 1) == 0) me = h2max4(me, y);
            else                   mo = h2max4(mo, y);
        }
        const uint4 m = h2max4(me, mo);

        if (nsel < end) {
            const float4 bias0 = __ldg((const float4*)(conv_b + g * 64 + l7 * 8));
            const float4 bias1 = __ldg((const float4*)(conv_b + g * 64 + l7 * 8 + 4));
            float2 c0 = __half22float2(*(const __half2*)&m.x);
            float2 c1 = __half22float2(*(const __half2*)&m.y);
            float2 c2 = __half22float2(*(const __half2*)&m.z);
            float2 c3 = __half22float2(*(const __half2*)&m.w);
            float4 o0, o1;
            o0.x = c0.x + bias0.x; o0.y = c0.y + bias0.y;
            o0.z = c1.x + bias0.z; o0.w = c1.y + bias0.w;
            o1.x = c2.x + bias1.x; o1.y = c2.y + bias1.y;
            o1.z = c3.x + bias1.z; o1.w = c3.y + bias1.w;
            float* op = out + (size_t)nsel * D_EMB + g * 64 + l7 * 8;
            *(float4*)op = o0;
            *(float4*)(op + 4) = o1;
        }
    }
}

// ---------------------------------------------------------------------------
extern "C" void kernel_launch(void* const* d_in, const int* in_sizes, int n_in,
                              void* d_out, int out_size) {
    const int* input = nullptr;
    const float* emb = nullptr;
    const float* conv_w = nullptr;
    const float* conv_b = nullptr;
    for (int i = 0; i < n_in; ++i) {
        switch (in_sizes[i]) {
            case 524288: input  = (const int*)d_in[i];   break;  // ids [128,256,16]
            case 33536:  emb    = (const float*)d_in[i]; break;  // [262,128]
            case 81920:  conv_w = (const float*)d_in[i]; break;  // [128,128,5]
            case 128:    conv_b = (const float*)d_in[i]; break;  // [128]
            default: break;  // lengths (32768) unused
        }
    }

    cudaFuncSetAttribute(conv_char_fused,
                         cudaFuncAttributeMaxDynamicSharedMemorySize, SMEM_BYTES);
    conv_char_fused<<<dim3(NCHUNK, 2), THREADS, SMEM_BYTES>>>(
        input, emb, conv_w, conv_b, (float*)d_out);
}